// round 1
// baseline (speedup 1.0000x reference)
#include <cuda_runtime.h>
#include <cstdint>
#include <cstddef>

#define BATCH 16
#define NTOK  1024
#define DDIM  256
#define ITERS 101   // 100 scan steps + 1 final sinkhorn_step (scale-invariance folds the rest)

// ---- static device scratch (no cudaMalloc allowed) ----
__device__ float g_K[(size_t)BATCH * NTOK * NTOK];   // 64 MB, L2-resident working set
__device__ float g_u[BATCH * NTOK];
__device__ float g_v[BATCH * NTOK];
__device__ float g_inorm[2 * BATCH * NTOK];          // [A rows | B rows] inverse L2 norms

__device__ __forceinline__ void cluster_sync_() {
    asm volatile("barrier.cluster.arrive.aligned;\n\t"
                 "barrier.cluster.wait.aligned;" ::: "memory");
}

// ================= 1) inverse L2 norms of all rows of fA, fB =================
__global__ void __launch_bounds__(256) norm_kernel(const float* __restrict__ fA,
                                                   const float* __restrict__ fB) {
    int gw = (blockIdx.x * 256 + threadIdx.x) >> 5;   // one warp per row
    int l  = threadIdx.x & 31;
    if (gw >= 2 * BATCH * NTOK) return;
    const float* src = (gw < BATCH * NTOK)
        ? fA + (size_t)gw * DDIM
        : fB + (size_t)(gw - BATCH * NTOK) * DDIM;
    float s = 0.f;
    #pragma unroll
    for (int k = l; k < DDIM; k += 32) { float x = src[k]; s += x * x; }
    #pragma unroll
    for (int o = 16; o > 0; o >>= 1) s += __shfl_xor_sync(0xffffffffu, s, o);
    if (l == 0) g_inorm[gw] = rsqrtf(fmaxf(s, 1e-12f));
}

// ====== 2) S = normalize(fA) @ normalize(fB)^T ; fused K = exp(5*clip(S)) ======
// 128x128 tile per CTA, BK=16, 256 threads, 8x8 microtile. grid (8,8,16).
__global__ void __launch_bounds__(256) gemm_kernel(const float* __restrict__ fA,
                                                   const float* __restrict__ fB,
                                                   float* __restrict__ S_out) {
    __shared__ __align__(16) float sA[16][132];
    __shared__ __align__(16) float sB[16][132];
    int batch = blockIdx.z;
    int ti = blockIdx.y, tj = blockIdx.x;
    int tid = threadIdx.x;
    int tx = tid & 15, ty = tid >> 4;

    const float* Ab = fA + ((size_t)batch * NTOK + (size_t)ti * 128) * DDIM;
    const float* Bb = fB + ((size_t)batch * NTOK + (size_t)tj * 128) * DDIM;
    int lrow = tid >> 2;
    int lkq  = (tid & 3) * 4;

    float acc[8][8];
    #pragma unroll
    for (int r = 0; r < 8; r++)
        #pragma unroll
        for (int c = 0; c < 8; c++) acc[r][c] = 0.f;

    for (int k0 = 0; k0 < DDIM; k0 += 16) {
        #pragma unroll
        for (int rr = 0; rr < 2; rr++) {
            int row = rr * 64 + lrow;
            float4 a = *(const float4*)&Ab[(size_t)row * DDIM + k0 + lkq];
            sA[lkq + 0][row] = a.x; sA[lkq + 1][row] = a.y;
            sA[lkq + 2][row] = a.z; sA[lkq + 3][row] = a.w;
            float4 b = *(const float4*)&Bb[(size_t)row * DDIM + k0 + lkq];
            sB[lkq + 0][row] = b.x; sB[lkq + 1][row] = b.y;
            sB[lkq + 2][row] = b.z; sB[lkq + 3][row] = b.w;
        }
        __syncthreads();
        #pragma unroll
        for (int k = 0; k < 16; k++) {
            float4 a0 = *(const float4*)&sA[k][ty * 8];
            float4 a1 = *(const float4*)&sA[k][ty * 8 + 4];
            float4 b0 = *(const float4*)&sB[k][tx * 8];
            float4 b1 = *(const float4*)&sB[k][tx * 8 + 4];
            float av[8] = {a0.x, a0.y, a0.z, a0.w, a1.x, a1.y, a1.z, a1.w};
            float bv[8] = {b0.x, b0.y, b0.z, b0.w, b1.x, b1.y, b1.z, b1.w};
            #pragma unroll
            for (int r = 0; r < 8; r++)
                #pragma unroll
                for (int c = 0; c < 8; c++) acc[r][c] += av[r] * bv[c];
        }
        __syncthreads();
    }

    // epilogue: apply inverse norms, emit S and K
    int row0 = ti * 128 + ty * 8;
    int col0 = tj * 128 + tx * 8;
    float ia[8], ib[8];
    #pragma unroll
    for (int r = 0; r < 8; r++) ia[r] = g_inorm[batch * NTOK + row0 + r];
    #pragma unroll
    for (int c = 0; c < 8; c++) ib[c] = g_inorm[BATCH * NTOK + batch * NTOK + col0 + c];

    #pragma unroll
    for (int r = 0; r < 8; r++) {
        size_t off = ((size_t)batch << 20) + (size_t)(row0 + r) * NTOK + col0;
        float sv[8], kv[8];
        #pragma unroll
        for (int c = 0; c < 8; c++) {
            float s = acc[r][c] * ia[r] * ib[c];
            sv[c] = s;
            float sc = fminf(fmaxf(s, -3.f), 3.f);   // clip(-S,-3,3) == -clip(S,-3,3)
            kv[c] = __expf(5.f * sc);                // exp(-LAM*C) = exp(5*clip(S))
        }
        float4 s0 = make_float4(sv[0], sv[1], sv[2], sv[3]);
        float4 s1 = make_float4(sv[4], sv[5], sv[6], sv[7]);
        *(float4*)&S_out[off]     = s0;
        *(float4*)&S_out[off + 4] = s1;
        float4 k0v = make_float4(kv[0], kv[1], kv[2], kv[3]);
        float4 k1v = make_float4(kv[4], kv[5], kv[6], kv[7]);
        *(float4*)&g_K[off]     = k0v;
        *(float4*)&g_K[off + 4] = k1v;
    }
}

// ====== 3) persistent sinkhorn: u = 1/(Kv), v = 1/(K^T u), 101 iters, + P out ======
// 16 clusters (one per batch) x 8 CTAs x 256 threads. Each CTA owns 128 rows (u-pass)
// and 128 cols (v-pass). cluster.sync between passes (release/acquire covers gmem).
__global__ void __cluster_dims__(8, 1, 1) __launch_bounds__(256, 1)
sinkhorn_kernel(float* __restrict__ P_out) {
    int b = blockIdx.x >> 3;
    int r = blockIdx.x & 7;
    const float* Kb = g_K + ((size_t)b << 20);
    float* ub = g_u + (b << 10);
    float* vb = g_v + (b << 10);
    int tid = threadIdx.x;
    int w = tid >> 5, l = tid & 31;

    __shared__ __align__(16) float s_vec[NTOK];
    __shared__ float4 s_part[8][32];

    for (int t = 0; t < ITERS; t++) {
        // ---- stage v (ones on first iteration) ----
        if (t == 0) { for (int i = tid; i < NTOK; i += 256) s_vec[i] = 1.f; }
        else        { for (int i = tid; i < NTOK; i += 256) s_vec[i] = vb[i]; }
        __syncthreads();

        // lane-resident v slice: lane l always uses v[4l+128k], k=0..7
        float4 vr[8];
        #pragma unroll
        for (int k = 0; k < 8; k++) vr[k] = *(const float4*)&s_vec[4 * (l + 32 * k)];

        // ---- u-pass: warp per row, rows [r*128 + w*16, +16) ----
        #pragma unroll 2
        for (int rr = 0; rr < 16; rr++) {
            int i = r * 128 + w * 16 + rr;
            const float4* Krow = (const float4*)(Kb + (size_t)i * NTOK);
            float sum = 0.f;
            #pragma unroll
            for (int k = 0; k < 8; k++) {
                float4 kk = Krow[l + 32 * k];
                sum += kk.x * vr[k].x + kk.y * vr[k].y + kk.z * vr[k].z + kk.w * vr[k].w;
            }
            #pragma unroll
            for (int o = 16; o > 0; o >>= 1) sum += __shfl_xor_sync(0xffffffffu, sum, o);
            if (l == 0) ub[i] = 1.f / sum;
        }
        cluster_sync_();

        // ---- stage u ----
        for (int i = tid; i < NTOK; i += 256) s_vec[i] = ub[i];
        __syncthreads();

        // ---- v-pass: cols [r*128, +128); warp w = i-split; lane = col quad ----
        const float4* K4 = (const float4*)Kb;
        float4 acc = make_float4(0.f, 0.f, 0.f, 0.f);
        int cbase = r * 32 + l;                 // float4 column index
        #pragma unroll 8
        for (int ii = 0; ii < 128; ii++) {
            int i = w * 128 + ii;
            float4 kk = K4[(size_t)i * 256 + cbase];
            float uu = s_vec[i];
            acc.x += kk.x * uu; acc.y += kk.y * uu;
            acc.z += kk.z * uu; acc.w += kk.w * uu;
        }
        s_part[w][l] = acc;
        __syncthreads();
        if (w == 0) {
            float4 a = s_part[0][l];
            #pragma unroll
            for (int s = 1; s < 8; s++) {
                float4 p = s_part[s][l];
                a.x += p.x; a.y += p.y; a.z += p.z; a.w += p.w;
            }
            int j = r * 128 + 4 * l;
            vb[j + 0] = 1.f / a.x; vb[j + 1] = 1.f / a.y;
            vb[j + 2] = 1.f / a.z; vb[j + 3] = 1.f / a.w;
        }
        cluster_sync_();
    }

    // ---- final P = diag(u) K diag(v), rows of this rank ----
    for (int i = tid; i < NTOK; i += 256) s_vec[i] = vb[i];
    __syncthreads();
    float4 vr[8];
    #pragma unroll
    for (int k = 0; k < 8; k++) vr[k] = *(const float4*)&s_vec[4 * (l + 32 * k)];
    #pragma unroll 1
    for (int rr = 0; rr < 16; rr++) {
        int i = r * 128 + w * 16 + rr;
        float ui = ub[i];
        const float4* Krow = (const float4*)(Kb + (size_t)i * NTOK);
        float4* dst = (float4*)(P_out + ((size_t)b << 20) + (size_t)i * NTOK);
        #pragma unroll
        for (int k = 0; k < 8; k++) {
            float4 kk = Krow[l + 32 * k];
            float4 o;
            o.x = ui * kk.x * vr[k].x; o.y = ui * kk.y * vr[k].y;
            o.z = ui * kk.z * vr[k].z; o.w = ui * kk.w * vr[k].w;
            dst[l + 32 * k] = o;
        }
    }
}

extern "C" void kernel_launch(void* const* d_in, const int* in_sizes, int n_in,
                              void* d_out, int out_size) {
    const float* fA = (const float*)d_in[0];
    const float* fB = (const float*)d_in[1];
    float* out = (float*)d_out;
    float* P = out;                                       // first half: P_out
    float* S = out + (size_t)BATCH * NTOK * NTOK;         // second half: Sij

    norm_kernel<<<(2 * BATCH * NTOK) / 8, 256>>>(fA, fB);
    dim3 g(8, 8, BATCH);
    gemm_kernel<<<g, 256>>>(fA, fB, S);
    sinkhorn_kernel<<<128, 256>>>(P);
}

// round 3
// speedup vs baseline: 1.1433x; 1.1433x over previous
#include <cuda_runtime.h>
#include <cuda_fp16.h>
#include <cstdint>
#include <cstddef>

#define BATCH 16
#define NTOK  1024
#define DDIM  256
#define ITERS 101   // 100 scan steps + 1 final sinkhorn_step (scale-invariance folds the rest)

// ---- static device scratch (no cudaMalloc allowed) ----
// K stored as fp16 (range [e^-5, e^5], safe): 32 MB, fully L2-resident.
__device__ float4 g_K4[(size_t)BATCH * NTOK * NTOK / 8];   // 8 halves per float4
__device__ float g_u[BATCH * NTOK];
__device__ float g_v[BATCH * NTOK];
__device__ float g_inorm[2 * BATCH * NTOK];                // [A rows | B rows] inv L2 norms

__device__ __forceinline__ void cluster_sync_() {
    asm volatile("barrier.cluster.arrive.aligned;\n\t"
                 "barrier.cluster.wait.aligned;" ::: "memory");
}

// ================= 1) inverse L2 norms of all rows of fA, fB =================
__global__ void __launch_bounds__(256) norm_kernel(const float* __restrict__ fA,
                                                   const float* __restrict__ fB) {
    int gw = (blockIdx.x * 256 + threadIdx.x) >> 5;   // one warp per row
    int l  = threadIdx.x & 31;
    if (gw >= 2 * BATCH * NTOK) return;
    const float* src = (gw < BATCH * NTOK)
        ? fA + (size_t)gw * DDIM
        : fB + (size_t)(gw - BATCH * NTOK) * DDIM;
    float s = 0.f;
    #pragma unroll
    for (int k = l; k < DDIM; k += 32) { float x = src[k]; s += x * x; }
    #pragma unroll
    for (int o = 16; o > 0; o >>= 1) s += __shfl_xor_sync(0xffffffffu, s, o);
    if (l == 0) g_inorm[gw] = rsqrtf(fmaxf(s, 1e-12f));
}

// ====== 2) S = normalize(fA) @ normalize(fB)^T ; fused K = exp(5*clip(S)) ======
// 128x128 tile per CTA, BK=16, 256 threads, 8x8 microtile. grid (8,8,16).
__global__ void __launch_bounds__(256) gemm_kernel(const float* __restrict__ fA,
                                                   const float* __restrict__ fB,
                                                   float* __restrict__ S_out) {
    __shared__ __align__(16) float sA[16][132];
    __shared__ __align__(16) float sB[16][132];
    int batch = blockIdx.z;
    int ti = blockIdx.y, tj = blockIdx.x;
    int tid = threadIdx.x;
    int tx = tid & 15, ty = tid >> 4;

    const float* Ab = fA + ((size_t)batch * NTOK + (size_t)ti * 128) * DDIM;
    const float* Bb = fB + ((size_t)batch * NTOK + (size_t)tj * 128) * DDIM;
    int lrow = tid >> 2;
    int lkq  = (tid & 3) * 4;

    float acc[8][8];
    #pragma unroll
    for (int r = 0; r < 8; r++)
        #pragma unroll
        for (int c = 0; c < 8; c++) acc[r][c] = 0.f;

    for (int k0 = 0; k0 < DDIM; k0 += 16) {
        #pragma unroll
        for (int rr = 0; rr < 2; rr++) {
            int row = rr * 64 + lrow;
            float4 a = *(const float4*)&Ab[(size_t)row * DDIM + k0 + lkq];
            sA[lkq + 0][row] = a.x; sA[lkq + 1][row] = a.y;
            sA[lkq + 2][row] = a.z; sA[lkq + 3][row] = a.w;
            float4 b = *(const float4*)&Bb[(size_t)row * DDIM + k0 + lkq];
            sB[lkq + 0][row] = b.x; sB[lkq + 1][row] = b.y;
            sB[lkq + 2][row] = b.z; sB[lkq + 3][row] = b.w;
        }
        __syncthreads();
        #pragma unroll
        for (int k = 0; k < 16; k++) {
            float4 a0 = *(const float4*)&sA[k][ty * 8];
            float4 a1 = *(const float4*)&sA[k][ty * 8 + 4];
            float4 b0 = *(const float4*)&sB[k][tx * 8];
            float4 b1 = *(const float4*)&sB[k][tx * 8 + 4];
            float av[8] = {a0.x, a0.y, a0.z, a0.w, a1.x, a1.y, a1.z, a1.w};
            float bv[8] = {b0.x, b0.y, b0.z, b0.w, b1.x, b1.y, b1.z, b1.w};
            #pragma unroll
            for (int r = 0; r < 8; r++)
                #pragma unroll
                for (int c = 0; c < 8; c++) acc[r][c] += av[r] * bv[c];
        }
        __syncthreads();
    }

    // epilogue: apply inverse norms, emit S (fp32) and K (fp16)
    int row0 = ti * 128 + ty * 8;
    int col0 = tj * 128 + tx * 8;
    float ia[8], ib[8];
    #pragma unroll
    for (int r = 0; r < 8; r++) ia[r] = g_inorm[batch * NTOK + row0 + r];
    #pragma unroll
    for (int c = 0; c < 8; c++) ib[c] = g_inorm[BATCH * NTOK + batch * NTOK + col0 + c];

    __half* Kh = (__half*)g_K4;
    #pragma unroll
    for (int r = 0; r < 8; r++) {
        size_t off = ((size_t)batch << 20) + (size_t)(row0 + r) * NTOK + col0;
        float sv[8], kv[8];
        #pragma unroll
        for (int c = 0; c < 8; c++) {
            float s = acc[r][c] * ia[r] * ib[c];
            sv[c] = s;
            float sc = fminf(fmaxf(s, -3.f), 3.f);   // clip(-S,-3,3) == -clip(S,-3,3)
            kv[c] = __expf(5.f * sc);                // exp(-LAM*C) = exp(5*clip(S))
        }
        *(float4*)&S_out[off]     = make_float4(sv[0], sv[1], sv[2], sv[3]);
        *(float4*)&S_out[off + 4] = make_float4(sv[4], sv[5], sv[6], sv[7]);
        float4 kp;
        ((__half2*)&kp)[0] = __floats2half2_rn(kv[0], kv[1]);
        ((__half2*)&kp)[1] = __floats2half2_rn(kv[2], kv[3]);
        ((__half2*)&kp)[2] = __floats2half2_rn(kv[4], kv[5]);
        ((__half2*)&kp)[3] = __floats2half2_rn(kv[6], kv[7]);
        *(float4*)&Kh[off] = kp;                     // off multiple of 8 -> 16B aligned
    }
}

// ====== 3) persistent sinkhorn on fp16 K: u = 1/(Kv), v = 1/(K^T u), 101 iters ======
// 16 clusters (one per batch) x 8 CTAs x 256 threads. Each CTA owns 128 rows (u-pass)
// and 128 cols (v-pass). cluster.sync between passes (arrive=release, wait=acquire).
__global__ void __cluster_dims__(8, 1, 1) __launch_bounds__(256, 1)
sinkhorn_kernel(float* __restrict__ P_out) {
    int b = blockIdx.x >> 3;
    int r = blockIdx.x & 7;
    const __half* Kb = (const __half*)g_K4 + ((size_t)b << 20);
    const float4* Kb4 = (const float4*)Kb;           // 128 float4 (8 halves each) per row
    float* ub = g_u + (b << 10);
    float* vb = g_v + (b << 10);
    int tid = threadIdx.x;
    int w = tid >> 5, l = tid & 31;

    __shared__ __align__(16) float s_vec[NTOK];
    __shared__ float s_red[16][16][9];               // [isplit][chunk_local][elem(+pad)]

    for (int t = 0; t < ITERS; t++) {
        // ---- stage v (ones on first iteration) ----
        if (t == 0) { for (int i = tid; i < NTOK; i += 256) s_vec[i] = 1.f; }
        else        { for (int i = tid; i < NTOK; i += 256) s_vec[i] = vb[i]; }
        __syncthreads();

        // lane-resident v slice: lane l uses half8-chunks c = l+32k, cols 8c..8c+7
        float vr[4][8];
        #pragma unroll
        for (int k = 0; k < 4; k++) {
            float4 v0 = *(const float4*)&s_vec[8 * (l + 32 * k)];
            float4 v1 = *(const float4*)&s_vec[8 * (l + 32 * k) + 4];
            vr[k][0] = v0.x; vr[k][1] = v0.y; vr[k][2] = v0.z; vr[k][3] = v0.w;
            vr[k][4] = v1.x; vr[k][5] = v1.y; vr[k][6] = v1.z; vr[k][7] = v1.w;
        }

        // ---- u-pass: warp per row, rows [r*128 + w*16, +16) ----
        #pragma unroll 2
        for (int rr = 0; rr < 16; rr++) {
            int i = r * 128 + w * 16 + rr;
            const float4* Krow = Kb4 + (size_t)i * 128;
            float sum = 0.f;
            #pragma unroll
            for (int k = 0; k < 4; k++) {
                float4 raw = Krow[l + 32 * k];
                const __half2* h = (const __half2*)&raw;
                float2 f0 = __half22float2(h[0]);
                float2 f1 = __half22float2(h[1]);
                float2 f2 = __half22float2(h[2]);
                float2 f3 = __half22float2(h[3]);
                sum += f0.x * vr[k][0] + f0.y * vr[k][1]
                     + f1.x * vr[k][2] + f1.y * vr[k][3]
                     + f2.x * vr[k][4] + f2.y * vr[k][5]
                     + f3.x * vr[k][6] + f3.y * vr[k][7];
            }
            #pragma unroll
            for (int o = 16; o > 0; o >>= 1) sum += __shfl_xor_sync(0xffffffffu, sum, o);
            if (l == 0) ub[i] = 1.f / sum;
        }
        cluster_sync_();

        // ---- stage u ----
        for (int i = tid; i < NTOK; i += 256) s_vec[i] = ub[i];
        __syncthreads();

        // ---- v-pass: CTA owns col chunks [16r, 16r+16); 16 i-splits x 16 chunks ----
        {
            int cl    = tid & 15;            // chunk within CTA
            int chunk = r * 16 + cl;         // global half8-chunk (cols 8*chunk..+8)
            int isplit = tid >> 4;           // 0..15, rows [64*isplit, +64)
            float acc[8];
            #pragma unroll
            for (int e = 0; e < 8; e++) acc[e] = 0.f;
            #pragma unroll 4
            for (int ii = 0; ii < 64; ii++) {
                int i = isplit * 64 + ii;
                float4 raw = Kb4[(size_t)i * 128 + chunk];
                float uu = s_vec[i];
                const __half2* h = (const __half2*)&raw;
                float2 f0 = __half22float2(h[0]);
                float2 f1 = __half22float2(h[1]);
                float2 f2 = __half22float2(h[2]);
                float2 f3 = __half22float2(h[3]);
                acc[0] += f0.x * uu; acc[1] += f0.y * uu;
                acc[2] += f1.x * uu; acc[3] += f1.y * uu;
                acc[4] += f2.x * uu; acc[5] += f2.y * uu;
                acc[6] += f3.x * uu; acc[7] += f3.y * uu;
            }
            #pragma unroll
            for (int e = 0; e < 8; e++) s_red[isplit][cl][e] = acc[e];
        }
        __syncthreads();
        if (tid < 128) {
            int cl = tid >> 3, e = tid & 7;
            float s = 0.f;
            #pragma unroll
            for (int is = 0; is < 16; is++) s += s_red[is][cl][e];
            vb[r * 128 + cl * 8 + e] = 1.f / s;
        }
        cluster_sync_();
    }

    // ---- final P = diag(u) K diag(v), rows of this rank ----
    for (int i = tid; i < NTOK; i += 256) s_vec[i] = vb[i];
    __syncthreads();
    float vr[4][8];
    #pragma unroll
    for (int k = 0; k < 4; k++) {
        float4 v0 = *(const float4*)&s_vec[8 * (l + 32 * k)];
        float4 v1 = *(const float4*)&s_vec[8 * (l + 32 * k) + 4];
        vr[k][0] = v0.x; vr[k][1] = v0.y; vr[k][2] = v0.z; vr[k][3] = v0.w;
        vr[k][4] = v1.x; vr[k][5] = v1.y; vr[k][6] = v1.z; vr[k][7] = v1.w;
    }
    #pragma unroll 1
    for (int rr = 0; rr < 16; rr++) {
        int i = r * 128 + w * 16 + rr;
        float ui = ub[i];
        const float4* Krow = Kb4 + (size_t)i * 128;
        float4* dst = (float4*)(P_out + ((size_t)b << 20) + (size_t)i * NTOK);
        #pragma unroll
        for (int k = 0; k < 4; k++) {
            float4 raw = Krow[l + 32 * k];
            const __half2* h = (const __half2*)&raw;
            float2 f0 = __half22float2(h[0]);
            float2 f1 = __half22float2(h[1]);
            float2 f2 = __half22float2(h[2]);
            float2 f3 = __half22float2(h[3]);
            float4 o0, o1;
            o0.x = ui * f0.x * vr[k][0]; o0.y = ui * f0.y * vr[k][1];
            o0.z = ui * f1.x * vr[k][2]; o0.w = ui * f1.y * vr[k][3];
            o1.x = ui * f2.x * vr[k][4]; o1.y = ui * f2.y * vr[k][5];
            o1.z = ui * f3.x * vr[k][6]; o1.w = ui * f3.y * vr[k][7];
            dst[2 * (l + 32 * k)]     = o0;
            dst[2 * (l + 32 * k) + 1] = o1;
        }
    }
}

extern "C" void kernel_launch(void* const* d_in, const int* in_sizes, int n_in,
                              void* d_out, int out_size) {
    const float* fA = (const float*)d_in[0];
    const float* fB = (const float*)d_in[1];
    float* out = (float*)d_out;
    float* P = out;                                       // first half: P_out
    float* S = out + (size_t)BATCH * NTOK * NTOK;         // second half: Sij

    norm_kernel<<<(2 * BATCH * NTOK) / 8, 256>>>(fA, fB);
    dim3 g(8, 8, BATCH);
    gemm_kernel<<<g, 256>>>(fA, fB, S);
    sinkhorn_kernel<<<128, 256>>>(P);
}